// round 5
// baseline (speedup 1.0000x reference)
#include <cuda_runtime.h>

// PointPillars pseudo-image: inverse-map (u16) + channel-split coalesced gather.
// Output: (B=16, C=64, NY=400, NX=400) float32 = 655 MB, fully written each call.

#define B_   16
#define C_   64
#define NY_  400
#define NX_  400
#define PLANE  (NY_ * NX_)      // 160,000 pixels per frame
#define NPIX   (B_ * PLANE)     // 2,560,000 total pixels
#define CSPLIT 4                // gridDim.y: channel groups per quad
#define CPT    (C_ / CSPLIT)    // 16 channels per thread

// pixel -> (local voxel index + 1), 0 = empty. 5.12 MB __device__ scratch.
__device__ unsigned short g_map[NPIX];

// ---------------------------------------------------------------------------
// 1) init map to 0 (int4 stores: 8 entries per store)
// ---------------------------------------------------------------------------
__global__ void init_map_kernel() {
    int i = blockIdx.x * blockDim.x + threadIdx.x;
    if (i < NPIX / 8) {
        reinterpret_cast<int4*>(g_map)[i] = make_int4(0, 0, 0, 0);
    }
}

// ---------------------------------------------------------------------------
// 2) scatter local voxel ids (+1) into the map (unique cells -> no races)
// ---------------------------------------------------------------------------
__global__ void scatter_map_kernel(const int* __restrict__ idx, int n, int nvb) {
    int i = blockIdx.x * blockDim.x + threadIdx.x;
    if (i < n) {
        int4 v = reinterpret_cast<const int4*>(idx)[i];  // (b, z, y, x)
        int local = i - v.x * nvb;                       // index within batch
        g_map[v.x * PLANE + v.z * NX_ + v.w] = (unsigned short)(local + 1);
    }
}

// ---------------------------------------------------------------------------
// 3) gather: thread = (quad of 4 x-pixels) x (16-channel group, blockIdx.y).
//    4x the warps of the monolithic version -> deeper outstanding-load window
//    to hide scattered feature-read latency. Store coalescing unchanged:
//    each warp channel-store covers 512 contiguous bytes.
// ---------------------------------------------------------------------------
__global__ void __launch_bounds__(256) gather_kernel(
    const float* __restrict__ feat, float* __restrict__ out, int nvb)
{
    int q = blockIdx.x * blockDim.x + threadIdx.x;   // quad id
    if (q >= NPIX / 4) return;

    int cbase = blockIdx.y * CPT;                    // this thread's channel group

    int p   = q * 4;                                 // flat pixel index
    int b   = p / PLANE;
    int rem = p - b * PLANE;                         // quad-aligned offset in plane

    ushort4 mv = *reinterpret_cast<const ushort4*>(g_map + p);
    int m0 = (int)mv.x, m1 = (int)mv.y, m2 = (int)mv.z, m3 = (int)mv.w;

    long long base = (long long)b * nvb - 1;         // row = base + m (when m>0)
    const float* f0 = feat + (base + m0) * C_ + cbase;
    const float* f1 = feat + (base + m1) * C_ + cbase;
    const float* f2 = feat + (base + m2) * C_ + cbase;
    const float* f3 = feat + (base + m3) * C_ + cbase;

    float* obase = out + (long long)b * C_ * PLANE + (long long)cbase * PLANE + rem;
    const float4 zero = make_float4(0.f, 0.f, 0.f, 0.f);

#pragma unroll
    for (int c = 0; c < CPT; c += 4) {
        float4 a0 = (m0 > 0) ? *reinterpret_cast<const float4*>(f0 + c) : zero;
        float4 a1 = (m1 > 0) ? *reinterpret_cast<const float4*>(f1 + c) : zero;
        float4 a2 = (m2 > 0) ? *reinterpret_cast<const float4*>(f2 + c) : zero;
        float4 a3 = (m3 > 0) ? *reinterpret_cast<const float4*>(f3 + c) : zero;

        float4 o;
        o.x = a0.x; o.y = a1.x; o.z = a2.x; o.w = a3.x;
        *reinterpret_cast<float4*>(obase + (long long)(c + 0) * PLANE) = o;
        o.x = a0.y; o.y = a1.y; o.z = a2.y; o.w = a3.y;
        *reinterpret_cast<float4*>(obase + (long long)(c + 1) * PLANE) = o;
        o.x = a0.z; o.y = a1.z; o.z = a2.z; o.w = a3.z;
        *reinterpret_cast<float4*>(obase + (long long)(c + 2) * PLANE) = o;
        o.x = a0.w; o.y = a1.w; o.z = a2.w; o.w = a3.w;
        *reinterpret_cast<float4*>(obase + (long long)(c + 3) * PLANE) = o;
    }
}

// ---------------------------------------------------------------------------
// launch
// ---------------------------------------------------------------------------
extern "C" void kernel_launch(void* const* d_in, const int* in_sizes, int n_in,
                              void* d_out, int out_size) {
    const float* feat = (const float*)d_in[0];      // (N, 64) float32
    const int*   idx  = (const int*)d_in[1];        // (N, 4)  int32
    float*       out  = (float*)d_out;              // (16, 64, 400, 400)

    int n_vox = in_sizes[1] / 4;
    int nvb   = n_vox / B_;                         // voxels per batch frame

    init_map_kernel<<<(NPIX / 8 + 255) / 256, 256>>>();
    scatter_map_kernel<<<(n_vox + 255) / 256, 256>>>(idx, n_vox, nvb);

    dim3 ggrid((NPIX / 4 + 255) / 256, CSPLIT);
    gather_kernel<<<ggrid, 256>>>(feat, out, nvb);
}

// round 6
// speedup vs baseline: 1.0445x; 1.0445x over previous
#include <cuda_runtime.h>

// PointPillars pseudo-image: inverse-map (u16) + coalesced gather with
// explicit load batching (16 LDG.128 in flight per thread per group).
// Output: (B=16, C=64, NY=400, NX=400) float32 = 655 MB, fully written.

#define B_   16
#define C_   64
#define NY_  400
#define NX_  400
#define PLANE  (NY_ * NX_)      // 160,000 pixels per frame
#define NPIX   (B_ * PLANE)     // 2,560,000 total pixels

// pixel -> (local voxel index + 1), 0 = empty. 5.12 MB __device__ scratch.
__device__ unsigned short g_map[NPIX];

// ---------------------------------------------------------------------------
// 1) init map to 0 (int4 stores: 8 entries per store)
// ---------------------------------------------------------------------------
__global__ void init_map_kernel() {
    int i = blockIdx.x * blockDim.x + threadIdx.x;
    if (i < NPIX / 8) {
        reinterpret_cast<int4*>(g_map)[i] = make_int4(0, 0, 0, 0);
    }
}

// ---------------------------------------------------------------------------
// 2) scatter local voxel ids (+1) into the map (unique cells -> no races)
// ---------------------------------------------------------------------------
__global__ void scatter_map_kernel(const int* __restrict__ idx, int n, int nvb) {
    int i = blockIdx.x * blockDim.x + threadIdx.x;
    if (i < n) {
        int4 v = reinterpret_cast<const int4*>(idx)[i];  // (b, z, y, x)
        int local = i - v.x * nvb;                       // index within batch
        g_map[v.x * PLANE + v.z * NX_ + v.w] = (unsigned short)(local + 1);
    }
}

// ---------------------------------------------------------------------------
// 3) gather: one thread per quad of 4 consecutive x-pixels, all 64 channels.
//    Channels processed in 4 groups of 16; per group ALL 16 feature LDG.128
//    are issued before any store -> 16 outstanding loads per thread to hide
//    DRAM latency (R4 profile: issue 10%, DRAM 70% => scoreboard-bound).
//    Store coalescing: per warp each channel-store covers 512 contiguous B.
// ---------------------------------------------------------------------------
__global__ void __launch_bounds__(256) gather_kernel(
    const float* __restrict__ feat, float* __restrict__ out, int nvb)
{
    int q = blockIdx.x * blockDim.x + threadIdx.x;   // quad id
    if (q >= NPIX / 4) return;

    int p   = q * 4;                                 // flat pixel index
    int b   = p / PLANE;
    int rem = p - b * PLANE;                         // quad-aligned offset in plane

    ushort4 mv = *reinterpret_cast<const ushort4*>(g_map + p);
    int m0 = (int)mv.x, m1 = (int)mv.y, m2 = (int)mv.z, m3 = (int)mv.w;

    long long base = (long long)b * nvb - 1;         // row = base + m (when m>0)
    const float* f0 = feat + (base + m0) * C_;
    const float* f1 = feat + (base + m1) * C_;
    const float* f2 = feat + (base + m2) * C_;
    const float* f3 = feat + (base + m3) * C_;

    float* obase = out + (long long)b * C_ * PLANE + rem;
    const float4 zero = make_float4(0.f, 0.f, 0.f, 0.f);

#pragma unroll
    for (int g = 0; g < 4; ++g) {                    // 4 groups x 16 channels
        int c0 = g * 16;

        float4 L0[4], L1[4], L2[4], L3[4];
        // ---- phase 1: issue all 16 loads (independent, batched) ----
#pragma unroll
        for (int k = 0; k < 4; ++k) {
            int c = c0 + k * 4;
            L0[k] = (m0 > 0) ? *reinterpret_cast<const float4*>(f0 + c) : zero;
            L1[k] = (m1 > 0) ? *reinterpret_cast<const float4*>(f1 + c) : zero;
            L2[k] = (m2 > 0) ? *reinterpret_cast<const float4*>(f2 + c) : zero;
            L3[k] = (m3 > 0) ? *reinterpret_cast<const float4*>(f3 + c) : zero;
        }
        // ---- phase 2: transpose + 16 coalesced stores ----
#pragma unroll
        for (int k = 0; k < 4; ++k) {
            int c = c0 + k * 4;
            float4 o;
            o.x = L0[k].x; o.y = L1[k].x; o.z = L2[k].x; o.w = L3[k].x;
            *reinterpret_cast<float4*>(obase + (long long)(c + 0) * PLANE) = o;
            o.x = L0[k].y; o.y = L1[k].y; o.z = L2[k].y; o.w = L3[k].y;
            *reinterpret_cast<float4*>(obase + (long long)(c + 1) * PLANE) = o;
            o.x = L0[k].z; o.y = L1[k].z; o.z = L2[k].z; o.w = L3[k].z;
            *reinterpret_cast<float4*>(obase + (long long)(c + 2) * PLANE) = o;
            o.x = L0[k].w; o.y = L1[k].w; o.z = L2[k].w; o.w = L3[k].w;
            *reinterpret_cast<float4*>(obase + (long long)(c + 3) * PLANE) = o;
        }
    }
}

// ---------------------------------------------------------------------------
// launch
// ---------------------------------------------------------------------------
extern "C" void kernel_launch(void* const* d_in, const int* in_sizes, int n_in,
                              void* d_out, int out_size) {
    const float* feat = (const float*)d_in[0];      // (N, 64) float32
    const int*   idx  = (const int*)d_in[1];        // (N, 4)  int32
    float*       out  = (float*)d_out;              // (16, 64, 400, 400)

    int n_vox = in_sizes[1] / 4;
    int nvb   = n_vox / B_;                         // voxels per batch frame

    init_map_kernel<<<(NPIX / 8 + 255) / 256, 256>>>();
    scatter_map_kernel<<<(n_vox + 255) / 256, 256>>>(idx, n_vox, nvb);
    gather_kernel<<<(NPIX / 4 + 255) / 256, 256>>>(feat, out, nvb);
}